// round 14
// baseline (speedup 1.0000x reference)
#include <cuda_runtime.h>
#include <math_constants.h>

// HierSoftmaxNLL: 16-ary array tree (N=10000, branch=16), parent(i)=(i-1)>>4.
// leaf(label) = num_internal + label (leaves = nodes [num_internal, N),
// label_order ascending). Per level: log_softmax over the sibling group of
// scores[:, node-1]; leaf log-prob = sum along root->leaf path.
// Output = mean over batch of -leaf_log_prob.
//
// Graph = memset(out,0) node + ONE path kernel (64 blocks x 256 thr).
// Per level (16 lanes/row): coalesced LDG (clamped index so the load issues
// before the bounds predicate) -> exp -> 4-round xor-shuffle sum; product of
// level sums, single log. Block tail: smem reduce -> one atomicAdd(out,
// partial * -1/batch). No reduce kernel, no counter, no fence (R12 showed
// the 32-thread reduce node costs ~1-2us; R6/R7 showed last-block tails are
// worse -- this tail is a single fire-and-forget atomic per block).

#define LANES_PER_ROW 16
#define BLOCK_THREADS 256
#define ROWS_PER_BLOCK (BLOCK_THREADS / LANES_PER_ROW)   // 16
#define MAX_DEPTH 4

__global__ void hiersoftmax_path_kernel(const float* __restrict__ scores,
                                        const int*   __restrict__ labels,
                                        float* __restrict__ out,
                                        int n_scores_per_row,  // 9999
                                        int batch,             // 1024
                                        int leaf_offset,       // num_internal
                                        float neg_inv_batch)   // -1/batch
{
    const int tid  = threadIdx.x;
    const int lane = tid & (LANES_PER_ROW - 1);
    const int grp  = tid >> 4;
    const int b    = blockIdx.x * ROWS_PER_BLOCK + grp;
    const bool row_valid = (b < batch);

    const float* row = scores + (size_t)(row_valid ? b : 0) * (size_t)n_scores_per_row;

    int node = row_valid ? (leaf_offset + labels[b]) : 0;

    float vpart = 0.0f;   // sum of v[pos] (nonzero on one lane per level)
    float prod  = 1.0f;   // product of per-level sum(exp(v))

    #pragma unroll
    for (int it = 0; it < MAX_DEPTH; ++it) {
        const bool active = (node > 0);
        const int nd   = active ? node : 1;
        const int g    = (nd - 1) >> 4;
        const int pos  = (nd - 1) & 15;
        const int idx  = (g << 4) + lane;

        // Issue the load with a clamped index; fix up with the predicate after.
        const int  idx_c  = min(idx, n_scores_per_row - 1);
        const bool in_rng = active && (idx < n_scores_per_row);
        float vld = __ldg(row + idx_c);
        float v   = in_rng ? vld : -CUDART_INF_F;

        float sum = __expf(v);            // exp(-inf) = 0 pads short group
        #pragma unroll
        for (int s = 1; s < LANES_PER_ROW; s <<= 1)
            sum += __shfl_xor_sync(0xFFFFFFFFu, sum, s);

        if (active && lane == pos) vpart += v;
        if (active)                prod  *= sum;

        node = active ? g : 0;
    }

    // Gather per-level v[pos] contributions across the 16 lanes
    #pragma unroll
    for (int s = 1; s < LANES_PER_ROW; s <<= 1)
        vpart += __shfl_xor_sync(0xFFFFFFFFu, vpart, s);

    float rowlp = row_valid ? (vpart - __logf(prod)) : 0.0f;

    // Merge the two rows of this warp, then block-reduce 8 warp values
    rowlp += __shfl_xor_sync(0xFFFFFFFFu, rowlp, 16);

    __shared__ float swarp[BLOCK_THREADS / 32];
    if ((tid & 31) == 0) swarp[tid >> 5] = rowlp;
    __syncthreads();

    if (tid == 0) {
        float acc = 0.0f;
        #pragma unroll
        for (int w = 0; w < BLOCK_THREADS / 32; ++w) acc += swarp[w];
        atomicAdd(out, acc * neg_inv_batch);   // out pre-zeroed by memset node
    }
}

extern "C" void kernel_launch(void* const* d_in, const int* in_sizes, int n_in,
                              void* d_out, int out_size) {
    // Inputs: scores, labels, flat_index, child_index, anc_matrix,
    //         label_order, num_internal, max_children
    const float* scores = (const float*)d_in[0];
    const int*   labels = (const int*)d_in[1];
    float*       out    = (float*)d_out;

    int batch = in_sizes[1];                      // 1024
    int n_scores_per_row = in_sizes[0] / batch;   // 9999
    int n_leaves = in_sizes[5];                   // 9375
    int leaf_offset = (n_scores_per_row + 1) - n_leaves;  // 625

    int n_blocks = (batch + ROWS_PER_BLOCK - 1) / ROWS_PER_BLOCK;  // 64

    // Zero the accumulator (graph-capturable memset node), then accumulate.
    cudaMemsetAsync(out, 0, sizeof(float));

    hiersoftmax_path_kernel<<<n_blocks, BLOCK_THREADS>>>(
        scores, labels, out, n_scores_per_row, batch, leaf_offset,
        -1.0f / (float)batch);
}